// round 3
// baseline (speedup 1.0000x reference)
#include <cuda_runtime.h>

// ---------------- problem constants ----------------------------------------
#define BGRAPH 1024
#define FN     32
#define DIN    64
#define HID    128
#define NHEADS 4
#define EPG    256
#define ETOT   (EPG + FN)       // 288
#define H4     (NHEADS * HID)   // 512
#define XPAD   132              // row-major padded stride for [32][128]
#define PPAD   516              // row-major padded stride for [32][512]
#define XTPAD  34               // transposed stride (even -> b64 aligned)
#define A1PAD  34               // dense alpha1 [4][32][34]
#define A2PAD  36               // dense alpha2 [32][36]
#define NTH    512

// ---------------- shared memory layout (float offsets) ---------------------
#define SM_XT   0                           // xT [128][34] -> later XP2 [32][132]
#define XT_SZ   (HID * XTPAD)               // 4352
#define SM_R1   XT_SZ                       // embT+AL -> XP1 [32][516] -> PART
#define R1_SZ   (FN * PPAD)                 // 16512
#define SM_R2   (SM_R1 + R1_SZ)             // H1T [512][34] -> OUT2 [32][132]
#define R2_SZ   (H4 * XTPAD)                // 17408
#define SM_AS1  (SM_R2 + R2_SZ)             // 38272
#define SM_AD1  (SM_AS1 + 128)
#define SM_DN1  (SM_AD1 + 128)
#define SM_AS2  (SM_DN1 + 128)
#define SM_AD2  (SM_AS2 + 32)
#define SM_DN2  (SM_AD2 + 32)
#define SM_A1   (SM_DN2 + 32)               // 38752: [4][32][34] = 4352
#define SM_A2   (SM_A1 + 4 * FN * A1PAD)    // 43104: [32][36] = 1152
#define SM_NF   (SM_A2 + FN * A2PAD)        // 44256 floats
#define SM_NI   (ETOT * 3 + (FN + 1) + FN)  // 929 ints
#define SMEM_BYTES ((SM_NF + SM_NI) * 4)

typedef unsigned long long ull;

__device__ __forceinline__ ull pk2(float x, float y) {
    ull r; asm("mov.b64 %0, {%1,%2};" : "=l"(r) : "f"(x), "f"(y)); return r;
}
__device__ __forceinline__ ull splat2(float x) { return pk2(x, x); }
__device__ __forceinline__ void upk2(ull p, float& x, float& y) {
    asm("mov.b64 {%0,%1}, %2;" : "=f"(x), "=f"(y) : "l"(p));
}
__device__ __forceinline__ void fma2(ull& d, ull a, ull b) {
    asm("fma.rn.f32x2 %0, %1, %2, %0;" : "+l"(d) : "l"(a), "l"(b));
}
__device__ __forceinline__ float dot4(const float4& a, const float4& b) {
    return fmaf(a.x, b.x, fmaf(a.y, b.y, fmaf(a.z, b.z, a.w * b.w)));
}
__device__ __forceinline__ float wredsum(float v) {
    #pragma unroll
    for (int o = 16; o; o >>= 1) v += __shfl_xor_sync(0xffffffffu, v, o);
    return v;
}
__device__ __forceinline__ float elu1(float x) {
    return (x > 0.f) ? x : expm1f(x);
}

__global__ __launch_bounds__(NTH, 1)
void gat_fused_kernel(
    const float* __restrict__ emb,    const float* __restrict__ Wal,
    const float* __restrict__ bal,    const float* __restrict__ lng,
    const float* __restrict__ lnb,    const float* __restrict__ gatel,
    const float* __restrict__ W1,     const float* __restrict__ as1w,
    const float* __restrict__ ad1w,   const float* __restrict__ b1,
    const float* __restrict__ W2,     const float* __restrict__ as2w,
    const float* __restrict__ ad2w,   const float* __restrict__ b2,
    const int*   __restrict__ esrc,   const int*   __restrict__ edst,
    float*       __restrict__ out,    int write_gate)
{
    extern __shared__ float sm[];
    float* xT   = sm + SM_XT;              // [128][34]
    float* XP2  = sm + SM_XT;              // later [32][132]
    float* embT = sm + SM_R1;              // [64][34]
    float* AL   = sm + SM_R1 + 64 * XTPAD; // [32][128]
    float* XP1  = sm + SM_R1;              // [32][516]
    float* PART = sm + SM_R1;              // 3*[32][128]
    float* H1T  = sm + SM_R2;              // [512][34]
    float* OUT2 = sm + SM_R2;              // later [32][132]
    float* as1  = sm + SM_AS1;
    float* ad1  = sm + SM_AD1;
    float* dn1  = sm + SM_DN1;
    float* as2  = sm + SM_AS2;
    float* ad2  = sm + SM_AD2;
    float* dn2  = sm + SM_DN2;
    float* A1   = sm + SM_A1;              // [4][32][34]  (h,s,d)
    float* A2   = sm + SM_A2;              // [32][36]     (s,d)
    int* sSL  = (int*)(sm + SM_NF);
    int* sDL  = sSL + ETOT;
    int* sEI  = sDL + ETOT;
    int* sOFF = sEI + ETOT;      // 33 (kept for CSR build symmetry)
    int* sCUR = sOFF + (FN + 1); // 32

    const int g    = blockIdx.x;
    const int tid  = threadIdx.x;
    const int lane = tid & 31;
    const int wid  = tid >> 5;

    // ---------- Phase 0: stage emb transposed, zero alpha/den --------------
    {
        float4 v = ((const float4*)emb)[(size_t)g * (FN * DIN / 4) + tid];
        int r  = tid >> 4;
        int c4 = tid & 15;
        embT[(c4 * 4 + 0) * XTPAD + r] = v.x;
        embT[(c4 * 4 + 1) * XTPAD + r] = v.y;
        embT[(c4 * 4 + 2) * XTPAD + r] = v.z;
        embT[(c4 * 4 + 3) * XTPAD + r] = v.w;
    }
    #pragma unroll
    for (int i = tid; i < 4 * FN * A1PAD; i += NTH) A1[i] = 0.f;
    if (tid < FN * A2PAD - NTH + 512) { }  // (noop)
    for (int i = tid; i < FN * A2PAD; i += NTH) A2[i] = 0.f;
    if (tid < 128) dn1[tid] = 0.f;
    if (tid < 32)  { dn2[tid] = 0.f; sCUR[tid] = 0; }
    __syncthreads();

    // ---------- Phase A: warps 0-7 align GEMM | warps 8-15 edge lists ------
    if (wid < 8) {
        ull acc[2][4];
        #pragma unroll
        for (int p = 0; p < 2; ++p)
            #pragma unroll
            for (int j = 0; j < 4; ++j) acc[p][j] = 0ULL;
        const float4* Wp = (const float4*)Wal + lane;
        #pragma unroll 4
        for (int k = 0; k < DIN; ++k) {
            float4 b = Wp[k * 32];
            ull b0 = splat2(b.x), b1v = splat2(b.y), b2v = splat2(b.z), b3 = splat2(b.w);
            const ull* ap = (const ull*)(embT + k * XTPAD + wid * 4);
            ull a0 = ap[0], a1 = ap[1];
            fma2(acc[0][0], a0, b0); fma2(acc[0][1], a0, b1v);
            fma2(acc[0][2], a0, b2v); fma2(acc[0][3], a0, b3);
            fma2(acc[1][0], a1, b0); fma2(acc[1][1], a1, b1v);
            fma2(acc[1][2], a1, b2v); fma2(acc[1][3], a1, b3);
        }
        float4 bb = ((const float4*)bal)[lane];
        #pragma unroll
        for (int p = 0; p < 2; ++p) {
            float4 r0, r1;
            upk2(acc[p][0], r0.x, r1.x); upk2(acc[p][1], r0.y, r1.y);
            upk2(acc[p][2], r0.z, r1.z); upk2(acc[p][3], r0.w, r1.w);
            r0.x += bb.x; r0.y += bb.y; r0.z += bb.z; r0.w += bb.w;
            r1.x += bb.x; r1.y += bb.y; r1.z += bb.z; r1.w += bb.w;
            int row = wid * 4 + p * 2;
            ((float4*)(AL + row * HID))[lane]       = r0;
            ((float4*)(AL + (row + 1) * HID))[lane] = r1;
        }
    } else {
        int t = tid - 256;                  // 0..255
        int s = esrc[g * EPG + t] - g * FN;
        int d = edst[g * EPG + t] - g * FN;
        sSL[t] = s; sDL[t] = d;
        if (t < FN) { sSL[EPG + t] = t; sDL[EPG + t] = t; }
    }
    __syncthreads();

    // ---------- Phase A2: LayerNorm + gate -> xT ---------------------------
    {
        #pragma unroll
        for (int rr = 0; rr < 2; ++rr) {
            int r = wid * 2 + rr;
            float v[4];
            float s = 0.f, s2 = 0.f;
            #pragma unroll
            for (int j = 0; j < 4; ++j) {
                v[j] = AL[r * HID + j * 32 + lane];
                s  += v[j];
                s2 += v[j] * v[j];
            }
            s  = wredsum(s);
            s2 = wredsum(s2);
            float mean = s * (1.f / HID);
            float var  = s2 * (1.f / HID) - mean * mean;
            float rstd = rsqrtf(var + 1e-5f);
            float gate = 1.f / (1.f + __expf(-gatel[r]));
            #pragma unroll
            for (int j = 0; j < 4; ++j) {
                int c = j * 32 + lane;
                xT[c * XTPAD + r] = ((v[j] - mean) * rstd * lng[c] + lnb[c]) * gate;
            }
        }
    }
    __syncthreads();

    // ---------- Phase B: conv1 GEMM (f32x2, grouped LDG) + att epilogue ----
    {
        const int rg = wid >> 2;
        const int h  = wid & 3;
        ull acc[4][4];
        #pragma unroll
        for (int p = 0; p < 4; ++p)
            #pragma unroll
            for (int j = 0; j < 4; ++j) acc[p][j] = 0ULL;
        const float4* Wp = (const float4*)W1 + h * 32 + lane;
        #pragma unroll 1
        for (int k0 = 0; k0 < HID; k0 += 4) {
            float4 bq[4];
            #pragma unroll
            for (int j = 0; j < 4; ++j) bq[j] = Wp[(k0 + j) * 128];
            #pragma unroll
            for (int j = 0; j < 4; ++j) {
                ull b0 = splat2(bq[j].x), b1v = splat2(bq[j].y);
                ull b2v = splat2(bq[j].z), b3 = splat2(bq[j].w);
                const ull* ap = (const ull*)(xT + (k0 + j) * XTPAD + rg * 8);
                ull a0 = ap[0], a1 = ap[1], a2 = ap[2], a3 = ap[3];
                fma2(acc[0][0], a0, b0); fma2(acc[0][1], a0, b1v);
                fma2(acc[0][2], a0, b2v); fma2(acc[0][3], a0, b3);
                fma2(acc[1][0], a1, b0); fma2(acc[1][1], a1, b1v);
                fma2(acc[1][2], a1, b2v); fma2(acc[1][3], a1, b3);
                fma2(acc[2][0], a2, b0); fma2(acc[2][1], a2, b1v);
                fma2(acc[2][2], a2, b2v); fma2(acc[2][3], a2, b3);
                fma2(acc[3][0], a3, b0); fma2(acc[3][1], a3, b1v);
                fma2(acc[3][2], a3, b2v); fma2(acc[3][3], a3, b3);
            }
        }
        float4 aw = ((const float4*)as1w)[h * 32 + lane];
        float4 dw = ((const float4*)ad1w)[h * 32 + lane];
        #pragma unroll
        for (int p = 0; p < 4; ++p) {
            float4 r0, r1;
            upk2(acc[p][0], r0.x, r1.x); upk2(acc[p][1], r0.y, r1.y);
            upk2(acc[p][2], r0.z, r1.z); upk2(acc[p][3], r0.w, r1.w);
            int row = rg * 8 + p * 2;
            ((float4*)(XP1 + row * PPAD + h * HID))[lane]       = r0;
            ((float4*)(XP1 + (row + 1) * PPAD + h * HID))[lane] = r1;
            float ss0 = wredsum(dot4(r0, aw));
            float dd0 = wredsum(dot4(r0, dw));
            float ss1 = wredsum(dot4(r1, aw));
            float dd1 = wredsum(dot4(r1, dw));
            if (lane == 0) {
                as1[row * 4 + h] = ss0;       ad1[row * 4 + h] = dd0;
                as1[(row + 1) * 4 + h] = ss1; ad1[(row + 1) * 4 + h] = dd1;
            }
        }
    }
    __syncthreads();

    // ---------- Edge pass 1: exp(leaky) -> dense A1 + den ------------------
    if (tid < ETOT) {
        int s = sSL[tid], d = sDL[tid];
        #pragma unroll
        for (int h = 0; h < NHEADS; ++h) {
            float l = as1[s * 4 + h] + ad1[d * 4 + h];
            l = (l > 0.f) ? l : 0.2f * l;
            float ex = __expf(l);
            atomicAdd(&A1[(h * FN + s) * A1PAD + d], ex);
            atomicAdd(&dn1[d * 4 + h], ex);
        }
    }
    __syncthreads();

    // ---------- Phase D: dense agg1 (f32x2) + bias + ELU -> H1T ------------
    {
        const int rg = wid >> 2;           // rows rg*8..+7
        const int h  = wid & 3;            // c = h*128 + j*32 + lane
        ull acc[4][4];                     // [row-pair][j]
        #pragma unroll
        for (int p = 0; p < 4; ++p)
            #pragma unroll
            for (int j = 0; j < 4; ++j) acc[p][j] = 0ULL;
        const float* xrow = XP1 + h * HID + lane;
        const ull*   arow = (const ull*)(A1 + h * FN * A1PAD + rg * 8);
        #pragma unroll 4
        for (int s = 0; s < FN; ++s) {
            ull sj0 = splat2(xrow[s * PPAD + 0]);
            ull sj1 = splat2(xrow[s * PPAD + 32]);
            ull sj2 = splat2(xrow[s * PPAD + 64]);
            ull sj3 = splat2(xrow[s * PPAD + 96]);
            const ull* ap = (const ull*)((const float*)arow + s * A1PAD);
            ull a0 = ap[0], a1 = ap[1], a2 = ap[2], a3 = ap[3];
            fma2(acc[0][0], a0, sj0); fma2(acc[0][1], a0, sj1);
            fma2(acc[0][2], a0, sj2); fma2(acc[0][3], a0, sj3);
            fma2(acc[1][0], a1, sj0); fma2(acc[1][1], a1, sj1);
            fma2(acc[1][2], a1, sj2); fma2(acc[1][3], a1, sj3);
            fma2(acc[2][0], a2, sj0); fma2(acc[2][1], a2, sj1);
            fma2(acc[2][2], a2, sj2); fma2(acc[2][3], a2, sj3);
            fma2(acc[3][0], a3, sj0); fma2(acc[3][1], a3, sj1);
            fma2(acc[3][2], a3, sj2); fma2(acc[3][3], a3, sj3);
        }
        float bc[4];
        #pragma unroll
        for (int j = 0; j < 4; ++j) bc[j] = b1[h * HID + j * 32 + lane];
        #pragma unroll
        for (int p = 0; p < 4; ++p) {
            int d0 = rg * 8 + p * 2;
            float i0 = __fdividef(1.f, dn1[d0 * 4 + h]);
            float i1 = __fdividef(1.f, dn1[(d0 + 1) * 4 + h]);
            #pragma unroll
            for (int j = 0; j < 4; ++j) {
                int c = h * HID + j * 32 + lane;
                float v0, v1;
                upk2(acc[p][j], v0, v1);
                v0 = elu1(fmaf(v0, i0, bc[j]));
                v1 = elu1(fmaf(v1, i1, bc[j]));
                *(ull*)(H1T + c * XTPAD + d0) = pk2(v0, v1);
            }
        }
    }
    __syncthreads();

    // ---------- Phase E: conv2 GEMM (f32x2, k-split 4, grouped LDG) --------
    {
        const int rg = wid & 3;
        const int ks = wid >> 2;
        ull acc[4][4];
        #pragma unroll
        for (int p = 0; p < 4; ++p)
            #pragma unroll
            for (int j = 0; j < 4; ++j) acc[p][j] = 0ULL;
        const float4* Wp = (const float4*)W2 + lane;
        const int k0base = ks * (H4 / 4);
        #pragma unroll 1
        for (int k0 = k0base; k0 < k0base + H4 / 4; k0 += 4) {
            float4 bq[4];
            #pragma unroll
            for (int j = 0; j < 4; ++j) bq[j] = Wp[(k0 + j) * 32];
            #pragma unroll
            for (int j = 0; j < 4; ++j) {
                ull b0 = splat2(bq[j].x), b1v = splat2(bq[j].y);
                ull b2v = splat2(bq[j].z), b3 = splat2(bq[j].w);
                const ull* ap = (const ull*)(H1T + (k0 + j) * XTPAD + rg * 8);
                ull a0 = ap[0], a1 = ap[1], a2 = ap[2], a3 = ap[3];
                fma2(acc[0][0], a0, b0); fma2(acc[0][1], a0, b1v);
                fma2(acc[0][2], a0, b2v); fma2(acc[0][3], a0, b3);
                fma2(acc[1][0], a1, b0); fma2(acc[1][1], a1, b1v);
                fma2(acc[1][2], a1, b2v); fma2(acc[1][3], a1, b3);
                fma2(acc[2][0], a2, b0); fma2(acc[2][1], a2, b1v);
                fma2(acc[2][2], a2, b2v); fma2(acc[2][3], a2, b3);
                fma2(acc[3][0], a3, b0); fma2(acc[3][1], a3, b1v);
                fma2(acc[3][2], a3, b2v); fma2(acc[3][3], a3, b3);
            }
        }
        if (ks > 0) {
            #pragma unroll
            for (int p = 0; p < 4; ++p) {
                float4 r0, r1;
                upk2(acc[p][0], r0.x, r1.x); upk2(acc[p][1], r0.y, r1.y);
                upk2(acc[p][2], r0.z, r1.z); upk2(acc[p][3], r0.w, r1.w);
                int row = rg * 8 + p * 2;
                ((float4*)(PART + (ks - 1) * 4096 + row * HID))[lane]       = r0;
                ((float4*)(PART + (ks - 1) * 4096 + (row + 1) * HID))[lane] = r1;
            }
        }
        __syncthreads();
        if (ks == 0) {
            float4 aw = ((const float4*)as2w)[lane];
            float4 dw = ((const float4*)ad2w)[lane];
            #pragma unroll
            for (int p = 0; p < 4; ++p) {
                float4 r0, r1;
                upk2(acc[p][0], r0.x, r1.x); upk2(acc[p][1], r0.y, r1.y);
                upk2(acc[p][2], r0.z, r1.z); upk2(acc[p][3], r0.w, r1.w);
                int row = rg * 8 + p * 2;
                #pragma unroll
                for (int q = 0; q < 3; ++q) {
                    float4 t0 = ((float4*)(PART + q * 4096 + row * HID))[lane];
                    float4 t1 = ((float4*)(PART + q * 4096 + (row + 1) * HID))[lane];
                    r0.x += t0.x; r0.y += t0.y; r0.z += t0.z; r0.w += t0.w;
                    r1.x += t1.x; r1.y += t1.y; r1.z += t1.z; r1.w += t1.w;
                }
                ((float4*)(XP2 + row * XPAD))[lane]       = r0;
                ((float4*)(XP2 + (row + 1) * XPAD))[lane] = r1;
                float ss0 = wredsum(dot4(r0, aw));
                float dd0 = wredsum(dot4(r0, dw));
                float ss1 = wredsum(dot4(r1, aw));
                float dd1 = wredsum(dot4(r1, dw));
                if (lane == 0) {
                    as2[row] = ss0;     ad2[row] = dd0;
                    as2[row + 1] = ss1; ad2[row + 1] = dd1;
                }
            }
        }
    }
    __syncthreads();

    // ---------- Edge pass 2 -> dense A2 + den ------------------------------
    if (tid < ETOT) {
        int s = sSL[tid], d = sDL[tid];
        float l = as2[s] + ad2[d];
        l = (l > 0.f) ? l : 0.2f * l;
        float ex = __expf(l);
        atomicAdd(&A2[s * A2PAD + d], ex);
        atomicAdd(&dn2[d], ex);
    }
    __syncthreads();

    // ---------- Phase G: dense agg2 + bias2 -> OUT2 ------------------------
    {
        const int d0 = wid * 2;            // rows d0, d0+1
        ull acc[4];
        #pragma unroll
        for (int j = 0; j < 4; ++j) acc[j] = 0ULL;
        const float* xrow = XP2 + lane;
        #pragma unroll 4
        for (int s = 0; s < FN; ++s) {
            ull ap = *(const ull*)(A2 + s * A2PAD + d0);
            ull s0 = splat2(xrow[s * XPAD + 0]);
            ull s1 = splat2(xrow[s * XPAD + 32]);
            ull s2 = splat2(xrow[s * XPAD + 64]);
            ull s3 = splat2(xrow[s * XPAD + 96]);
            fma2(acc[0], ap, s0); fma2(acc[1], ap, s1);
            fma2(acc[2], ap, s2); fma2(acc[3], ap, s3);
        }
        float i0 = __fdividef(1.f, dn2[d0]);
        float i1 = __fdividef(1.f, dn2[d0 + 1]);
        #pragma unroll
        for (int j = 0; j < 4; ++j) {
            int c = j * 32 + lane;
            float bb = b2[c];
            float v0, v1;
            upk2(acc[j], v0, v1);
            OUT2[d0 * XPAD + c]       = fmaf(v0, i0, bb);
            OUT2[(d0 + 1) * XPAD + c] = fmaf(v1, i1, bb);
        }
    }
    __syncthreads();

    // ---------- Phase H: mean pool -> out ----------------------------------
    if (tid < HID) {
        float s = 0.f;
        #pragma unroll
        for (int n = 0; n < FN; ++n) s += OUT2[n * XPAD + tid];
        out[(size_t)g * HID + tid] = s * (1.f / FN);
    }
    if (write_gate && g == 0 && tid < FN) {
        out[(size_t)BGRAPH * HID + tid] = 1.f / (1.f + __expf(-gatel[tid]));
    }
}

extern "C" void kernel_launch(void* const* d_in, const int* in_sizes, int n_in,
                              void* d_out, int out_size)
{
    const float* emb   = (const float*)d_in[0];
    const float* Wal   = (const float*)d_in[1];
    const float* bal   = (const float*)d_in[2];
    const float* lng   = (const float*)d_in[3];
    const float* lnb   = (const float*)d_in[4];
    const float* gatel = (const float*)d_in[5];
    const float* W1    = (const float*)d_in[6];
    const float* as1w  = (const float*)d_in[7];
    const float* ad1w  = (const float*)d_in[8];
    const float* b1    = (const float*)d_in[9];
    const float* W2    = (const float*)d_in[10];
    const float* as2w  = (const float*)d_in[11];
    const float* ad2w  = (const float*)d_in[12];
    const float* b2    = (const float*)d_in[13];
    const int*   ei    = (const int*)d_in[14];

    const int Et = in_sizes[14] / 2;
    const int* esrc = ei;
    const int* edst = ei + Et;
    const int write_gate = (out_size >= BGRAPH * HID + FN) ? 1 : 0;

    cudaFuncSetAttribute(gat_fused_kernel,
                         cudaFuncAttributeMaxDynamicSharedMemorySize, SMEM_BYTES);

    gat_fused_kernel<<<BGRAPH, NTH, SMEM_BYTES>>>(
        emb, Wal, bal, lng, lnb, gatel,
        W1, as1w, ad1w, b1, W2, as2w, ad2w, b2,
        esrc, edst, (float*)d_out, write_gate);
}

// round 5
// speedup vs baseline: 1.0496x; 1.0496x over previous
#include <cuda_runtime.h>

// ---------------- problem constants ----------------------------------------
#define BGRAPH 1024
#define FN     32
#define DIN    64
#define HID    128
#define NHEADS 4
#define EPG    256
#define ETOT   (EPG + FN)       // 288
#define H4     (NHEADS * HID)   // 512
#define XPAD   132
#define H1PAD  516
#define YTPAD  34
#define A1PAD  34
#define A2PAD  36
#define NTH    512

// ---------------- shared memory layout (float offsets) ---------------------
#define SM_YT   0                     // yT [4][128][34] = 17408 (overlays embT, AL)
#define SM_EMBT 0                     // embT [64][34] = 2176
#define SM_ALN  2176                  // AL [32][128] = 4096
#define SM_H1   17408                 // h1 [32][516] = 16512 (overlays x [32][132])
#define SM_A1   33920                 // [4][32][34] = 4352
#define SM_A2   38272                 // [32][36] = 1152
#define SM_INV1 39424                 // 128
#define SM_INV2 39552                 // 32
#define SM_AS1  39584                 // 128
#define SM_AD1  39712                 // 128
#define SM_AS2  39840                 // 32
#define SM_AD2  39872                 // 32
#define SM_CS   39904                 // 32
#define SM_ZB   39936                 // 512
#define SM_PS   40448                 // 512
#define SM_WTS1 40960                 // 512
#define SM_WTD1 41472                 // 512
#define SM_WT2S 41984                 // 512
#define SM_WT2D 42496                 // 512
#define SM_NF   43008
#define SM_NI   (2 * ETOT)            // sSL, sDL
#define SMEM_BYTES ((SM_NF + SM_NI) * 4)

typedef unsigned long long ull;

__device__ float g_wts1[512];   // [h][k] = sum_c W1[k, h*128+c] * att_src1[h,c]
__device__ float g_wtd1[512];
__device__ float g_wt2s[512];   // [k]    = sum_c W2[k,c] * att_src2[c]
__device__ float g_wt2d[512];

__device__ __forceinline__ ull pk2(float x, float y) {
    ull r; asm("mov.b64 %0, {%1,%2};" : "=l"(r) : "f"(x), "f"(y)); return r;
}
__device__ __forceinline__ ull splat2(float x) { return pk2(x, x); }
__device__ __forceinline__ void upk2(ull p, float& x, float& y) {
    asm("mov.b64 {%0,%1}, %2;" : "=f"(x), "=f"(y) : "l"(p));
}
__device__ __forceinline__ void fma2(ull& d, ull a, ull b) {
    asm("fma.rn.f32x2 %0, %1, %2, %0;" : "+l"(d) : "l"(a), "l"(b));
}
__device__ __forceinline__ void mul2(ull& d, ull b) {
    asm("mul.rn.f32x2 %0, %0, %1;" : "+l"(d) : "l"(b));
}
__device__ __forceinline__ float dot4(const float4& a, const float4& b) {
    return fmaf(a.x, b.x, fmaf(a.y, b.y, fmaf(a.z, b.z, a.w * b.w)));
}
__device__ __forceinline__ float wredsum(float v) {
    #pragma unroll
    for (int o = 16; o; o >>= 1) v += __shfl_xor_sync(0xffffffffu, v, o);
    return v;
}
__device__ __forceinline__ float elu1(float x) {
    return (x > 0.f) ? x : expm1f(x);
}

// ---------------- pre-kernel: project attention vectors through weights ----
__global__ void precomp_kernel(const float* __restrict__ W1,
                               const float* __restrict__ as1w,
                               const float* __restrict__ ad1w,
                               const float* __restrict__ W2,
                               const float* __restrict__ as2w,
                               const float* __restrict__ ad2w)
{
    int t = blockIdx.x * blockDim.x + threadIdx.x;   // 0..1023
    if (t < 512) {
        int h = t >> 7, k = t & 127;
        const float* wrow = W1 + k * H4 + h * HID;
        const float* aw = as1w + h * HID;
        const float* dw = ad1w + h * HID;
        float s = 0.f, d = 0.f;
        #pragma unroll 4
        for (int c = 0; c < HID; ++c) {
            s = fmaf(wrow[c], aw[c], s);
            d = fmaf(wrow[c], dw[c], d);
        }
        g_wts1[t] = s; g_wtd1[t] = d;
    } else {
        int k = t - 512;
        const float* wrow = W2 + k * HID;
        float s = 0.f, d = 0.f;
        #pragma unroll 4
        for (int c = 0; c < HID; ++c) {
            s = fmaf(wrow[c], as2w[c], s);
            d = fmaf(wrow[c], ad2w[c], d);
        }
        g_wt2s[k] = s; g_wt2d[k] = d;
    }
}

__global__ __launch_bounds__(NTH, 1)
void gat_fused_kernel(
    const float* __restrict__ emb,    const float* __restrict__ Wal,
    const float* __restrict__ bal,    const float* __restrict__ lng,
    const float* __restrict__ lnb,    const float* __restrict__ gatel,
    const float* __restrict__ W1,     const float* __restrict__ b1,
    const float* __restrict__ W2,     const float* __restrict__ b2,
    const int*   __restrict__ esrc,   const int*   __restrict__ edst,
    float*       __restrict__ out,    int write_gate)
{
    extern __shared__ float sm[];
    float* embT = sm + SM_EMBT;           // [64][34]
    float* AL   = sm + SM_ALN;            // [32][128]
    float* yT   = sm + SM_YT;             // [4][128][34]
    float* X    = sm + SM_H1;             // x [32][132] (dies before h1)
    float* H1   = sm + SM_H1;             // h1 [32][516]
    float* A1   = sm + SM_A1;
    float* A2   = sm + SM_A2;
    float* inv1 = sm + SM_INV1;
    float* inv2 = sm + SM_INV2;
    float* as1  = sm + SM_AS1;
    float* ad1  = sm + SM_AD1;
    float* as2  = sm + SM_AS2;
    float* ad2  = sm + SM_AD2;
    float* cs   = sm + SM_CS;
    float* zb   = sm + SM_ZB;
    float* ps   = sm + SM_PS;
    float* wts1 = sm + SM_WTS1;
    float* wtd1 = sm + SM_WTD1;
    float* wt2s = sm + SM_WT2S;
    float* wt2d = sm + SM_WT2D;
    int* sSL = (int*)(sm + SM_NF);
    int* sDL = sSL + ETOT;

    const int g    = blockIdx.x;
    const int tid  = threadIdx.x;
    const int lane = tid & 31;
    const int wid  = tid >> 5;

    // ---------- Phase 0: stage embT + wt vectors, zero accumulators --------
    {
        float4 v = ((const float4*)emb)[(size_t)g * (FN * DIN / 4) + tid];
        int r  = tid >> 4;
        int c4 = tid & 15;
        embT[(c4 * 4 + 0) * YTPAD + r] = v.x;
        embT[(c4 * 4 + 1) * YTPAD + r] = v.y;
        embT[(c4 * 4 + 2) * YTPAD + r] = v.z;
        embT[(c4 * 4 + 3) * YTPAD + r] = v.w;
    }
    wts1[tid] = g_wts1[tid];
    wtd1[tid] = g_wtd1[tid];
    wt2s[tid] = g_wt2s[tid];
    wt2d[tid] = g_wt2d[tid];
    for (int i = tid; i < 4 * FN * A1PAD; i += NTH) A1[i] = 0.f;
    for (int i = tid; i < FN * A2PAD; i += NTH)     A2[i] = 0.f;
    if (tid < 32) { as2[tid] = 0.f; ad2[tid] = 0.f; }
    __syncthreads();

    // ---------- Phase 1: warps 0-7 align GEMM | warps 8-15 edge lists ------
    if (wid < 8) {
        ull acc[2][4];
        #pragma unroll
        for (int p = 0; p < 2; ++p)
            #pragma unroll
            for (int j = 0; j < 4; ++j) acc[p][j] = 0ULL;
        const float4* Wp = (const float4*)Wal + lane;
        #pragma unroll 4
        for (int k = 0; k < DIN; ++k) {
            float4 b = Wp[k * 32];
            ull b0 = splat2(b.x), b1v = splat2(b.y), b2v = splat2(b.z), b3 = splat2(b.w);
            const ull* ap = (const ull*)(embT + k * YTPAD + wid * 4);
            ull a0 = ap[0], a1 = ap[1];
            fma2(acc[0][0], a0, b0); fma2(acc[0][1], a0, b1v);
            fma2(acc[0][2], a0, b2v); fma2(acc[0][3], a0, b3);
            fma2(acc[1][0], a1, b0); fma2(acc[1][1], a1, b1v);
            fma2(acc[1][2], a1, b2v); fma2(acc[1][3], a1, b3);
        }
        float4 bb = ((const float4*)bal)[lane];
        #pragma unroll
        for (int p = 0; p < 2; ++p) {
            float4 r0, r1;
            upk2(acc[p][0], r0.x, r1.x); upk2(acc[p][1], r0.y, r1.y);
            upk2(acc[p][2], r0.z, r1.z); upk2(acc[p][3], r0.w, r1.w);
            r0.x += bb.x; r0.y += bb.y; r0.z += bb.z; r0.w += bb.w;
            r1.x += bb.x; r1.y += bb.y; r1.z += bb.z; r1.w += bb.w;
            int row = wid * 4 + p * 2;
            ((float4*)(AL + row * HID))[lane]       = r0;
            ((float4*)(AL + (row + 1) * HID))[lane] = r1;
        }
    } else {
        int t = tid - 256;                  // 0..255
        int s = esrc[g * EPG + t] - g * FN;
        int d = edst[g * EPG + t] - g * FN;
        sSL[t] = s; sDL[t] = d;
        if (t < FN) { sSL[EPG + t] = t; sDL[EPG + t] = t; }
    }
    __syncthreads();

    // ---------- Phase 2: LayerNorm + gate -> X; fused logits1 --------------
    {
        #pragma unroll
        for (int rr = 0; rr < 2; ++rr) {
            int r = wid * 2 + rr;
            float v[4];
            float s = 0.f, s2 = 0.f;
            #pragma unroll
            for (int j = 0; j < 4; ++j) {
                v[j] = AL[r * HID + j * 32 + lane];
                s  += v[j];
                s2 += v[j] * v[j];
            }
            s  = wredsum(s);
            s2 = wredsum(s2);
            float mean = s * (1.f / HID);
            float var  = s2 * (1.f / HID) - mean * mean;
            float rstd = rsqrtf(var + 1e-5f);
            float gate = 1.f / (1.f + __expf(-gatel[r]));
            float ss[4] = {0.f, 0.f, 0.f, 0.f};
            float dd[4] = {0.f, 0.f, 0.f, 0.f};
            #pragma unroll
            for (int j = 0; j < 4; ++j) {
                int c = j * 32 + lane;
                float xc = ((v[j] - mean) * rstd * lng[c] + lnb[c]) * gate;
                X[r * XPAD + c] = xc;
                #pragma unroll
                for (int h = 0; h < 4; ++h) {
                    ss[h] = fmaf(xc, wts1[h * HID + c], ss[h]);
                    dd[h] = fmaf(xc, wtd1[h * HID + c], dd[h]);
                }
            }
            #pragma unroll
            for (int h = 0; h < 4; ++h) {
                float s1 = wredsum(ss[h]);
                float d1 = wredsum(dd[h]);
                if (lane == 0) { as1[r * 4 + h] = s1; ad1[r * 4 + h] = d1; }
            }
        }
    }
    __syncthreads();

    // ---------- Phase 3: edge pass 1 -> dense A1 ---------------------------
    if (tid < ETOT) {
        int s = sSL[tid], d = sDL[tid];
        #pragma unroll
        for (int h = 0; h < NHEADS; ++h) {
            float l = as1[s * 4 + h] + ad1[d * 4 + h];
            l = (l > 0.f) ? l : 0.2f * l;
            atomicAdd(&A1[(h * FN + s) * A1PAD + d], __expf(l));
        }
    }
    __syncthreads();
    if (tid < 128) {
        int h = tid >> 5, d = tid & 31;
        float sum = 0.f;
        #pragma unroll 4
        for (int s = 0; s < FN; ++s) sum += A1[(h * FN + s) * A1PAD + d];
        inv1[d * 4 + h] = __fdividef(1.f, sum);
    }
    __syncthreads();

    // ---------- Phase 4: y = A1n^T @ x  (f32x2 over dst-pairs) -> yT -------
    {
        const int h  = wid >> 2;
        const int kg = wid & 3;
        const int k  = kg * 32 + lane;
        ull acc[16];
        #pragma unroll
        for (int p = 0; p < 16; ++p) acc[p] = 0ULL;
        #pragma unroll 2
        for (int s = 0; s < FN; ++s) {
            ull b = splat2(X[s * XPAD + k]);
            const ull* ar = (const ull*)(A1 + (h * FN + s) * A1PAD);
            #pragma unroll
            for (int p = 0; p < 16; ++p) fma2(acc[p], ar[p], b);
        }
        float* ybase = yT + (h * HID + k) * YTPAD;
        #pragma unroll
        for (int p = 0; p < 16; ++p) {
            ull iv = pk2(inv1[(2 * p) * 4 + h], inv1[(2 * p + 1) * 4 + h]);
            mul2(acc[p], iv);
            *(ull*)(ybase + 2 * p) = acc[p];
        }
    }
    __syncthreads();

    // ---------- Phase 5: h1 = ELU(y @ W1 + b1); fused logits2 partials -----
    // acc[p][j] maps to column h*128 + lane*4 + j  (float4 component mapping!)
    {
        const int rg = wid >> 2;
        const int h  = wid & 3;
        ull acc[4][4];
        #pragma unroll
        for (int p = 0; p < 4; ++p)
            #pragma unroll
            for (int j = 0; j < 4; ++j) acc[p][j] = 0ULL;
        const float4* Wp = (const float4*)W1 + h * 32 + lane;
        const float* yh = yT + h * HID * YTPAD + rg * 8;
        #pragma unroll 1
        for (int k0 = 0; k0 < HID; k0 += 4) {
            float4 bq[4];
            #pragma unroll
            for (int j = 0; j < 4; ++j) bq[j] = Wp[(k0 + j) * 128];
            #pragma unroll
            for (int j = 0; j < 4; ++j) {
                ull b0 = splat2(bq[j].x), b1v = splat2(bq[j].y);
                ull b2v = splat2(bq[j].z), b3 = splat2(bq[j].w);
                const ull* ap = (const ull*)(yh + (k0 + j) * YTPAD);
                ull a0 = ap[0], a1 = ap[1], a2 = ap[2], a3 = ap[3];
                fma2(acc[0][0], a0, b0); fma2(acc[0][1], a0, b1v);
                fma2(acc[0][2], a0, b2v); fma2(acc[0][3], a0, b3);
                fma2(acc[1][0], a1, b0); fma2(acc[1][1], a1, b1v);
                fma2(acc[1][2], a1, b2v); fma2(acc[1][3], a1, b3);
                fma2(acc[2][0], a2, b0); fma2(acc[2][1], a2, b1v);
                fma2(acc[2][2], a2, b2v); fma2(acc[2][3], a2, b3);
                fma2(acc[3][0], a3, b0); fma2(acc[3][1], a3, b1v);
                fma2(acc[3][2], a3, b2v); fma2(acc[3][3], a3, b3);
            }
        }
        float4 bb  = ((const float4*)b1)[h * 32 + lane];
        float4 w2s = ((const float4*)wt2s)[h * 32 + lane];
        float4 w2d = ((const float4*)wt2d)[h * 32 + lane];
        #pragma unroll
        for (int p = 0; p < 4; ++p) {
            int d0 = rg * 8 + p * 2;
            float4 r0, r1;
            upk2(acc[p][0], r0.x, r1.x); upk2(acc[p][1], r0.y, r1.y);
            upk2(acc[p][2], r0.z, r1.z); upk2(acc[p][3], r0.w, r1.w);
            r0.x = elu1(r0.x + bb.x); r0.y = elu1(r0.y + bb.y);
            r0.z = elu1(r0.z + bb.z); r0.w = elu1(r0.w + bb.w);
            r1.x = elu1(r1.x + bb.x); r1.y = elu1(r1.y + bb.y);
            r1.z = elu1(r1.z + bb.z); r1.w = elu1(r1.w + bb.w);
            ((float4*)(H1 + d0 * H1PAD + h * HID))[lane]       = r0;
            ((float4*)(H1 + (d0 + 1) * H1PAD + h * HID))[lane] = r1;
            float s0  = wredsum(dot4(r0, w2s));
            float d0s = wredsum(dot4(r0, w2d));
            float s1  = wredsum(dot4(r1, w2s));
            float d1s = wredsum(dot4(r1, w2d));
            if (lane == 0) {
                atomicAdd(&as2[d0], s0);
                atomicAdd(&ad2[d0], d0s);
                atomicAdd(&as2[d0 + 1], s1);
                atomicAdd(&ad2[d0 + 1], d1s);
            }
        }
    }
    __syncthreads();

    // ---------- Phase 6: edge pass 2 -> dense A2 ---------------------------
    if (tid < ETOT) {
        int s = sSL[tid], d = sDL[tid];
        float l = as2[s] + ad2[d];
        l = (l > 0.f) ? l : 0.2f * l;
        atomicAdd(&A2[s * A2PAD + d], __expf(l));
    }
    __syncthreads();
    if (tid < 32) {
        float sum = 0.f;
        #pragma unroll 4
        for (int s = 0; s < FN; ++s) sum += A2[s * A2PAD + tid];
        inv2[tid] = __fdividef(1.f, sum);
    }
    __syncthreads();
    if (tid < 32) {               // c[s] = (1/FN) * sum_d A2[s,d] * inv2[d]
        float acc = 0.f;
        #pragma unroll 4
        for (int d = 0; d < FN; ++d) acc = fmaf(A2[tid * A2PAD + d], inv2[d], acc);
        cs[tid] = acc * (1.f / FN);
    }
    __syncthreads();

    // ---------- Phase 7: zbar[k] = sum_s c[s] * h1[s,k] --------------------
    {
        float acc = 0.f;
        #pragma unroll 4
        for (int s = 0; s < FN; ++s) acc = fmaf(cs[s], H1[s * H1PAD + tid], acc);
        zb[tid] = acc;
    }
    __syncthreads();

    // ---------- Phase 8: out = zbar @ W2 + b2 ------------------------------
    {
        const int cc = tid & 127;
        const int ks = tid >> 7;             // 4 k-splits of 128
        const float* w2 = W2 + (ks * 128) * HID + cc;
        const float* zp = zb + ks * 128;
        float a0 = 0.f, a1 = 0.f, a2 = 0.f, a3 = 0.f;
        #pragma unroll 8
        for (int k = 0; k < 128; k += 4) {
            a0 = fmaf(zp[k + 0], w2[(k + 0) * HID], a0);
            a1 = fmaf(zp[k + 1], w2[(k + 1) * HID], a1);
            a2 = fmaf(zp[k + 2], w2[(k + 2) * HID], a2);
            a3 = fmaf(zp[k + 3], w2[(k + 3) * HID], a3);
        }
        ps[tid] = (a0 + a1) + (a2 + a3);
    }
    __syncthreads();
    if (tid < HID) {
        float tot = ps[tid] + ps[128 + tid] + ps[256 + tid] + ps[384 + tid];
        out[(size_t)g * HID + tid] = tot + b2[tid];
    }
    if (write_gate && g == 0 && tid < FN) {
        out[(size_t)BGRAPH * HID + tid] = 1.f / (1.f + __expf(-gatel[tid]));
    }
}

extern "C" void kernel_launch(void* const* d_in, const int* in_sizes, int n_in,
                              void* d_out, int out_size)
{
    const float* emb   = (const float*)d_in[0];
    const float* Wal   = (const float*)d_in[1];
    const float* bal   = (const float*)d_in[2];
    const float* lng   = (const float*)d_in[3];
    const float* lnb   = (const float*)d_in[4];
    const float* gatel = (const float*)d_in[5];
    const float* W1    = (const float*)d_in[6];
    const float* as1w  = (const float*)d_in[7];
    const float* ad1w  = (const float*)d_in[8];
    const float* b1    = (const float*)d_in[9];
    const float* W2    = (const float*)d_in[10];
    const float* as2w  = (const float*)d_in[11];
    const float* ad2w  = (const float*)d_in[12];
    const float* b2    = (const float*)d_in[13];
    const int*   ei    = (const int*)d_in[14];

    const int Et = in_sizes[14] / 2;
    const int* esrc = ei;
    const int* edst = ei + Et;
    const int write_gate = (out_size >= BGRAPH * HID + FN) ? 1 : 0;

    cudaFuncSetAttribute(gat_fused_kernel,
                         cudaFuncAttributeMaxDynamicSharedMemorySize, SMEM_BYTES);

    precomp_kernel<<<2, 512>>>(W1, as1w, ad1w, W2, as2w, ad2w);
    gat_fused_kernel<<<BGRAPH, NTH, SMEM_BYTES>>>(
        emb, Wal, bal, lng, lnb, gatel,
        W1, b1, W2, b2,
        esrc, edst, (float*)d_out, write_gate);
}

// round 6
// speedup vs baseline: 1.0503x; 1.0007x over previous
#include <cuda_runtime.h>

// ---------------- problem constants ----------------------------------------
#define BGRAPH 1024
#define FN     32
#define DIN    64
#define HID    128
#define NHEADS 4
#define EPG    256
#define ETOT   (EPG + FN)       // 288
#define H4     (NHEADS * HID)   // 512
#define XPAD   132
#define H1PAD  516
#define YTPAD  34
#define A1PAD  34
#define A2PAD  36
#define NTH    1024

// ---------------- shared memory layout (float offsets) ---------------------
#define SM_YT   0                     // yT [4][128][34] = 17408 (overlays embT, AL)
#define SM_EMBT 0                     // embT [64][34] = 2176
#define SM_ALN  2176                  // AL [32][128] = 4096
#define SM_H1   17408                 // h1 [32][516] = 16512 (overlays X [32][132])
#define SM_A1   33920                 // [4][32][34] = 4352
#define SM_A2   38272                 // [32][36] = 1152
#define SM_INV1 39424                 // 128
#define SM_INV2 39552                 // 32
#define SM_AS1  39584                 // 128
#define SM_AD1  39712                 // 128
#define SM_AS2  39840                 // 32
#define SM_AD2  39872                 // 32
#define SM_CS   39904                 // 32
#define SM_ZB   39936                 // 512
#define SM_PS   40448                 // 1024
#define SM_WTS1 41472                 // 512
#define SM_WTD1 41984                 // 512
#define SM_WT2S 42496                 // 512
#define SM_WT2D 43008                 // 512
#define SM_NF   43520
#define SM_NI   (2 * ETOT)            // sSL, sDL
#define SMEM_BYTES ((SM_NF + SM_NI) * 4)

typedef unsigned long long ull;

__device__ float g_wts1[512];   // [h][k] = sum_c W1[k, h*128+c] * att_src1[h,c]
__device__ float g_wtd1[512];
__device__ float g_wt2s[512];   // [k]    = sum_c W2[k,c] * att_src2[c]
__device__ float g_wt2d[512];

__device__ __forceinline__ ull pk2(float x, float y) {
    ull r; asm("mov.b64 %0, {%1,%2};" : "=l"(r) : "f"(x), "f"(y)); return r;
}
__device__ __forceinline__ ull splat2(float x) { return pk2(x, x); }
__device__ __forceinline__ void upk2(ull p, float& x, float& y) {
    asm("mov.b64 {%0,%1}, %2;" : "=f"(x), "=f"(y) : "l"(p));
}
__device__ __forceinline__ void fma2(ull& d, ull a, ull b) {
    asm("fma.rn.f32x2 %0, %1, %2, %0;" : "+l"(d) : "l"(a), "l"(b));
}
__device__ __forceinline__ void mul2(ull& d, ull b) {
    asm("mul.rn.f32x2 %0, %0, %1;" : "+l"(d) : "l"(b));
}
__device__ __forceinline__ float dot4(const float4& a, const float4& b) {
    return fmaf(a.x, b.x, fmaf(a.y, b.y, fmaf(a.z, b.z, a.w * b.w)));
}
__device__ __forceinline__ float wredsum(float v) {
    #pragma unroll
    for (int o = 16; o; o >>= 1) v += __shfl_xor_sync(0xffffffffu, v, o);
    return v;
}
__device__ __forceinline__ float elu1(float x) {
    return (x > 0.f) ? x : expm1f(x);
}

// ---------------- pre-kernel: project attention vectors through weights ----
__global__ void precomp_kernel(const float* __restrict__ W1,
                               const float* __restrict__ as1w,
                               const float* __restrict__ ad1w,
                               const float* __restrict__ W2,
                               const float* __restrict__ as2w,
                               const float* __restrict__ ad2w)
{
    int t = blockIdx.x * blockDim.x + threadIdx.x;   // 0..1023
    if (t < 512) {
        int h = t >> 7, k = t & 127;
        const float* wrow = W1 + k * H4 + h * HID;
        const float* aw = as1w + h * HID;
        const float* dw = ad1w + h * HID;
        float s = 0.f, d = 0.f;
        #pragma unroll 4
        for (int c = 0; c < HID; ++c) {
            s = fmaf(wrow[c], aw[c], s);
            d = fmaf(wrow[c], dw[c], d);
        }
        g_wts1[t] = s; g_wtd1[t] = d;
    } else {
        int k = t - 512;
        const float* wrow = W2 + k * HID;
        float s = 0.f, d = 0.f;
        #pragma unroll 4
        for (int c = 0; c < HID; ++c) {
            s = fmaf(wrow[c], as2w[c], s);
            d = fmaf(wrow[c], ad2w[c], d);
        }
        g_wt2s[k] = s; g_wt2d[k] = d;
    }
}

__global__ __launch_bounds__(NTH, 1)
void gat_fused_kernel(
    const float* __restrict__ emb,    const float* __restrict__ Wal,
    const float* __restrict__ bal,    const float* __restrict__ lng,
    const float* __restrict__ lnb,    const float* __restrict__ gatel,
    const float* __restrict__ W1,     const float* __restrict__ b1,
    const float* __restrict__ W2,     const float* __restrict__ b2,
    const int*   __restrict__ esrc,   const int*   __restrict__ edst,
    float*       __restrict__ out,    int write_gate)
{
    extern __shared__ float sm[];
    float* embT = sm + SM_EMBT;           // [64][34]
    float* AL   = sm + SM_ALN;            // [32][128]
    float* yT   = sm + SM_YT;             // [4][128][34]
    float* X    = sm + SM_H1;             // x [32][132] (dies before h1)
    float* H1   = sm + SM_H1;             // h1 [32][516]
    float* A1   = sm + SM_A1;
    float* A2   = sm + SM_A2;
    float* inv1 = sm + SM_INV1;
    float* inv2 = sm + SM_INV2;
    float* as1  = sm + SM_AS1;
    float* ad1  = sm + SM_AD1;
    float* as2  = sm + SM_AS2;
    float* ad2  = sm + SM_AD2;
    float* cs   = sm + SM_CS;
    float* zb   = sm + SM_ZB;
    float* ps   = sm + SM_PS;
    float* wts1 = sm + SM_WTS1;
    float* wtd1 = sm + SM_WTD1;
    float* wt2s = sm + SM_WT2S;
    float* wt2d = sm + SM_WT2D;
    int* sSL = (int*)(sm + SM_NF);
    int* sDL = sSL + ETOT;

    const int g    = blockIdx.x;
    const int tid  = threadIdx.x;
    const int lane = tid & 31;
    const int wid  = tid >> 5;

    // ---------- Phase 0: stage embT + wt vectors + edges, zero accums ------
    if (tid < 512) {
        float4 v = ((const float4*)emb)[(size_t)g * (FN * DIN / 4) + tid];
        int r  = tid >> 4;
        int c4 = tid & 15;
        embT[(c4 * 4 + 0) * YTPAD + r] = v.x;
        embT[(c4 * 4 + 1) * YTPAD + r] = v.y;
        embT[(c4 * 4 + 2) * YTPAD + r] = v.z;
        embT[(c4 * 4 + 3) * YTPAD + r] = v.w;
        wts1[tid] = g_wts1[tid];
        wtd1[tid] = g_wtd1[tid];
        wt2s[tid] = g_wt2s[tid];
        wt2d[tid] = g_wt2d[tid];
    } else if (tid < 768) {
        int t = tid - 512;                  // 0..255 template edges
        sSL[t] = esrc[g * EPG + t] - g * FN;
        sDL[t] = edst[g * EPG + t] - g * FN;
    } else if (tid < 800) {
        int t = tid - 768;                  // self loops
        sSL[EPG + t] = t;
        sDL[EPG + t] = t;
    }
    for (int i = tid; i < 4 * FN * A1PAD; i += NTH) A1[i] = 0.f;
    for (int i = tid; i < FN * A2PAD; i += NTH)     A2[i] = 0.f;
    if (tid < 32) { as2[tid] = 0.f; ad2[tid] = 0.f; }
    __syncthreads();

    // ---------- Phase 1: align GEMM (16 warps, 2 rows each) ----------------
    if (wid < 16) {
        ull acc[4];
        #pragma unroll
        for (int j = 0; j < 4; ++j) acc[j] = 0ULL;
        const float4* Wp = (const float4*)Wal + lane;
        #pragma unroll 4
        for (int k = 0; k < DIN; ++k) {
            float4 b = Wp[k * 32];
            ull a0 = *(const ull*)(embT + k * YTPAD + wid * 2);
            fma2(acc[0], a0, splat2(b.x));
            fma2(acc[1], a0, splat2(b.y));
            fma2(acc[2], a0, splat2(b.z));
            fma2(acc[3], a0, splat2(b.w));
        }
        float4 bb = ((const float4*)bal)[lane];
        float4 r0, r1;
        upk2(acc[0], r0.x, r1.x); upk2(acc[1], r0.y, r1.y);
        upk2(acc[2], r0.z, r1.z); upk2(acc[3], r0.w, r1.w);
        r0.x += bb.x; r0.y += bb.y; r0.z += bb.z; r0.w += bb.w;
        r1.x += bb.x; r1.y += bb.y; r1.z += bb.z; r1.w += bb.w;
        ((float4*)(AL + (wid * 2) * HID))[lane]     = r0;
        ((float4*)(AL + (wid * 2 + 1) * HID))[lane] = r1;
    }
    __syncthreads();

    // ---------- Phase 2: LayerNorm + gate -> X; fused logits1 (1 row/warp) -
    {
        const int r = wid;
        float v[4];
        float s = 0.f, s2 = 0.f;
        #pragma unroll
        for (int j = 0; j < 4; ++j) {
            v[j] = AL[r * HID + j * 32 + lane];
            s  += v[j];
            s2 += v[j] * v[j];
        }
        s  = wredsum(s);
        s2 = wredsum(s2);
        float mean = s * (1.f / HID);
        float var  = s2 * (1.f / HID) - mean * mean;
        float rstd = rsqrtf(var + 1e-5f);
        float gate = 1.f / (1.f + __expf(-gatel[r]));
        float ss[4] = {0.f, 0.f, 0.f, 0.f};
        float dd[4] = {0.f, 0.f, 0.f, 0.f};
        #pragma unroll
        for (int j = 0; j < 4; ++j) {
            int c = j * 32 + lane;
            float xc = ((v[j] - mean) * rstd * lng[c] + lnb[c]) * gate;
            X[r * XPAD + c] = xc;
            #pragma unroll
            for (int h = 0; h < 4; ++h) {
                ss[h] = fmaf(xc, wts1[h * HID + c], ss[h]);
                dd[h] = fmaf(xc, wtd1[h * HID + c], dd[h]);
            }
        }
        #pragma unroll
        for (int h = 0; h < 4; ++h) {
            float s1 = wredsum(ss[h]);
            float d1 = wredsum(dd[h]);
            if (lane == 0) { as1[r * 4 + h] = s1; ad1[r * 4 + h] = d1; }
        }
    }
    __syncthreads();

    // ---------- Phase 3: edge pass 1 -> dense A1 ---------------------------
    if (tid < ETOT) {
        int s = sSL[tid], d = sDL[tid];
        #pragma unroll
        for (int h = 0; h < NHEADS; ++h) {
            float l = as1[s * 4 + h] + ad1[d * 4 + h];
            l = (l > 0.f) ? l : 0.2f * l;
            atomicAdd(&A1[(h * FN + s) * A1PAD + d], __expf(l));
        }
    }
    __syncthreads();
    if (tid < 128) {
        int h = tid >> 5, d = tid & 31;
        float sum = 0.f;
        #pragma unroll 4
        for (int s = 0; s < FN; ++s) sum += A1[(h * FN + s) * A1PAD + d];
        inv1[d * 4 + h] = __fdividef(1.f, sum);
    }
    __syncthreads();

    // ---------- Phase 4: y = A1n^T @ x (16 warps) -> yT --------------------
    if (wid < 16) {
        const int h  = wid >> 2;
        const int kg = wid & 3;
        const int k  = kg * 32 + lane;
        ull acc[16];
        #pragma unroll
        for (int p = 0; p < 16; ++p) acc[p] = 0ULL;
        #pragma unroll 2
        for (int s = 0; s < FN; ++s) {
            ull b = splat2(X[s * XPAD + k]);
            const ull* ar = (const ull*)(A1 + (h * FN + s) * A1PAD);
            #pragma unroll
            for (int p = 0; p < 16; ++p) fma2(acc[p], ar[p], b);
        }
        float* ybase = yT + (h * HID + k) * YTPAD;
        #pragma unroll
        for (int p = 0; p < 16; ++p) {
            ull iv = pk2(inv1[(2 * p) * 4 + h], inv1[(2 * p + 1) * 4 + h]);
            mul2(acc[p], iv);
            *(ull*)(ybase + 2 * p) = acc[p];
        }
    }
    __syncthreads();

    // ---------- Phase 5: h1 = ELU(y @ W1 + b1) (32 warps, 4 rows each) -----
    // acc[p][j] maps to column h*128 + lane*4 + j (float4 component mapping)
    {
        const int rg = wid >> 2;            // 0..7 -> rows rg*4..+3
        const int h  = wid & 3;
        ull acc[2][4];
        #pragma unroll
        for (int p = 0; p < 2; ++p)
            #pragma unroll
            for (int j = 0; j < 4; ++j) acc[p][j] = 0ULL;
        const float4* Wp = (const float4*)W1 + h * 32 + lane;
        const float* yh = yT + h * HID * YTPAD + rg * 4;
        #pragma unroll 1
        for (int k0 = 0; k0 < HID; k0 += 4) {
            float4 bq[4];
            #pragma unroll
            for (int j = 0; j < 4; ++j) bq[j] = Wp[(k0 + j) * 128];
            #pragma unroll
            for (int j = 0; j < 4; ++j) {
                ull b0 = splat2(bq[j].x), b1v = splat2(bq[j].y);
                ull b2v = splat2(bq[j].z), b3 = splat2(bq[j].w);
                const ull* ap = (const ull*)(yh + (k0 + j) * YTPAD);
                ull a0 = ap[0], a1 = ap[1];
                fma2(acc[0][0], a0, b0); fma2(acc[0][1], a0, b1v);
                fma2(acc[0][2], a0, b2v); fma2(acc[0][3], a0, b3);
                fma2(acc[1][0], a1, b0); fma2(acc[1][1], a1, b1v);
                fma2(acc[1][2], a1, b2v); fma2(acc[1][3], a1, b3);
            }
        }
        float4 bb  = ((const float4*)b1)[h * 32 + lane];
        float4 w2s = ((const float4*)wt2s)[h * 32 + lane];
        float4 w2d = ((const float4*)wt2d)[h * 32 + lane];
        #pragma unroll
        for (int p = 0; p < 2; ++p) {
            int d0 = rg * 4 + p * 2;
            float4 r0, r1;
            upk2(acc[p][0], r0.x, r1.x); upk2(acc[p][1], r0.y, r1.y);
            upk2(acc[p][2], r0.z, r1.z); upk2(acc[p][3], r0.w, r1.w);
            r0.x = elu1(r0.x + bb.x); r0.y = elu1(r0.y + bb.y);
            r0.z = elu1(r0.z + bb.z); r0.w = elu1(r0.w + bb.w);
            r1.x = elu1(r1.x + bb.x); r1.y = elu1(r1.y + bb.y);
            r1.z = elu1(r1.z + bb.z); r1.w = elu1(r1.w + bb.w);
            ((float4*)(H1 + d0 * H1PAD + h * HID))[lane]       = r0;
            ((float4*)(H1 + (d0 + 1) * H1PAD + h * HID))[lane] = r1;
            float s0  = wredsum(dot4(r0, w2s));
            float d0s = wredsum(dot4(r0, w2d));
            float s1  = wredsum(dot4(r1, w2s));
            float d1s = wredsum(dot4(r1, w2d));
            if (lane == 0) {
                atomicAdd(&as2[d0], s0);
                atomicAdd(&ad2[d0], d0s);
                atomicAdd(&as2[d0 + 1], s1);
                atomicAdd(&ad2[d0 + 1], d1s);
            }
        }
    }
    __syncthreads();

    // ---------- Phase 6: edge pass 2 -> dense A2 ---------------------------
    if (tid < ETOT) {
        int s = sSL[tid], d = sDL[tid];
        float l = as2[s] + ad2[d];
        l = (l > 0.f) ? l : 0.2f * l;
        atomicAdd(&A2[s * A2PAD + d], __expf(l));
    }
    __syncthreads();
    if (tid < 32) {
        float sum = 0.f;
        #pragma unroll 4
        for (int s = 0; s < FN; ++s) sum += A2[s * A2PAD + tid];
        inv2[tid] = __fdividef(1.f, sum);
    }
    __syncthreads();
    if (tid < 32) {               // c[s] = (1/FN) * sum_d A2[s,d] * inv2[d]
        float acc = 0.f;
        #pragma unroll 4
        for (int d = 0; d < FN; ++d) acc = fmaf(A2[tid * A2PAD + d], inv2[d], acc);
        cs[tid] = acc * (1.f / FN);
    }
    __syncthreads();

    // ---------- Phase 7: zbar[k] = sum_s c[s] * h1[s,k] --------------------
    if (tid < 512) {
        float acc = 0.f;
        #pragma unroll 4
        for (int s = 0; s < FN; ++s) acc = fmaf(cs[s], H1[s * H1PAD + tid], acc);
        zb[tid] = acc;
    }
    __syncthreads();

    // ---------- Phase 8: out = zbar @ W2 + b2 (8-way k-split) --------------
    {
        const int cc = tid & 127;
        const int ks = tid >> 7;             // 8 k-splits of 64
        const float* w2 = W2 + (ks * 64) * HID + cc;
        const float* zp = zb + ks * 64;
        float a0 = 0.f, a1 = 0.f, a2 = 0.f, a3 = 0.f;
        #pragma unroll 4
        for (int k = 0; k < 64; k += 4) {
            a0 = fmaf(zp[k + 0], w2[(k + 0) * HID], a0);
            a1 = fmaf(zp[k + 1], w2[(k + 1) * HID], a1);
            a2 = fmaf(zp[k + 2], w2[(k + 2) * HID], a2);
            a3 = fmaf(zp[k + 3], w2[(k + 3) * HID], a3);
        }
        ps[tid] = (a0 + a1) + (a2 + a3);
    }
    __syncthreads();
    if (tid < HID) {
        float tot = 0.f;
        #pragma unroll
        for (int q = 0; q < 8; ++q) tot += ps[q * 128 + tid];
        out[(size_t)g * HID + tid] = tot + b2[tid];
    }
    if (write_gate && g == 0 && tid < FN) {
        out[(size_t)BGRAPH * HID + tid] = 1.f / (1.f + __expf(-gatel[tid]));
    }
}

extern "C" void kernel_launch(void* const* d_in, const int* in_sizes, int n_in,
                              void* d_out, int out_size)
{
    const float* emb   = (const float*)d_in[0];
    const float* Wal   = (const float*)d_in[1];
    const float* bal   = (const float*)d_in[2];
    const float* lng   = (const float*)d_in[3];
    const float* lnb   = (const float*)d_in[4];
    const float* gatel = (const float*)d_in[5];
    const float* W1    = (const float*)d_in[6];
    const float* as1w  = (const float*)d_in[7];
    const float* ad1w  = (const float*)d_in[8];
    const float* b1    = (const float*)d_in[9];
    const float* W2    = (const float*)d_in[10];
    const float* as2w  = (const float*)d_in[11];
    const float* ad2w  = (const float*)d_in[12];
    const float* b2    = (const float*)d_in[13];
    const int*   ei    = (const int*)d_in[14];

    const int Et = in_sizes[14] / 2;
    const int* esrc = ei;
    const int* edst = ei + Et;
    const int write_gate = (out_size >= BGRAPH * HID + FN) ? 1 : 0;

    cudaFuncSetAttribute(gat_fused_kernel,
                         cudaFuncAttributeMaxDynamicSharedMemorySize, SMEM_BYTES);

    precomp_kernel<<<2, 512>>>(W1, as1w, ad1w, W2, as2w, ad2w);
    gat_fused_kernel<<<BGRAPH, NTH, SMEM_BYTES>>>(
        emb, Wal, bal, lng, lnb, gatel,
        W1, b1, W2, b2,
        esrc, edst, (float*)d_out, write_gate);
}